// round 7
// baseline (speedup 1.0000x reference)
#include <cuda_runtime.h>
#include <cuda_bf16.h>
#include <cstdint>

#define NB 32
#define NS 4096
#define ND 512
#define NU 512
#define NM (NB * NS)

// ---------------- device scratch ----------------
__device__ float g_score_part[4][NB * NS];   // per-coltile score partials
__device__ float g_decp[NB * NU];
__device__ float g_ctx_part[32 * NB * ND];
__device__ __nv_bfloat16 g_enc_hi[(size_t)NM * ND];
__device__ __nv_bfloat16 g_enc_lo[(size_t)NM * ND];
__device__ __nv_bfloat16 g_w1t_hi[NU * ND];
__device__ __nv_bfloat16 g_w1t_lo[NU * ND];

// ---------------- helpers ----------------
static __device__ __forceinline__ uint32_t smem_u32(const void* p) {
    uint32_t a;
    asm("{ .reg .u64 t; cvta.to.shared.u64 t, %1; cvt.u32.u64 %0, t; }" : "=r"(a) : "l"(p));
    return a;
}
static __device__ __forceinline__ void ldmx4(uint32_t* r, uint32_t addr) {
    asm volatile("ldmatrix.sync.aligned.m8n8.x4.shared.b16 {%0,%1,%2,%3}, [%4];"
                 : "=r"(r[0]), "=r"(r[1]), "=r"(r[2]), "=r"(r[3]) : "r"(addr));
}
static __device__ __forceinline__ void mma_bf16(float* c, const uint32_t* a, const uint32_t* b) {
    asm volatile(
        "mma.sync.aligned.m16n8k16.row.col.f32.bf16.bf16.f32 "
        "{%0,%1,%2,%3}, {%4,%5,%6,%7}, {%8,%9}, {%0,%1,%2,%3};"
        : "+f"(c[0]), "+f"(c[1]), "+f"(c[2]), "+f"(c[3])
        : "r"(a[0]), "r"(a[1]), "r"(a[2]), "r"(a[3]), "r"(b[0]), "r"(b[1]));
}
static __device__ __forceinline__ void cp16(uint32_t s, const void* g) {
    asm volatile("cp.async.cg.shared.global [%0], [%1], 16;" :: "r"(s), "l"(g));
}
#define CP_COMMIT() asm volatile("cp.async.commit_group;" ::: "memory")
#define CP_WAIT1()  asm volatile("cp.async.wait_group 1;" ::: "memory")
#define CP_WAIT0()  asm volatile("cp.async.wait_group 0;" ::: "memory")

static __device__ __forceinline__ uint32_t sw64(uint32_t o) { return o ^ ((o >> 3) & 0x30); }
static __device__ __forceinline__ uint32_t pack2(float x, float y) {
    __nv_bfloat162 t = __floats2bfloat162_rn(x, y);
    return *(uint32_t*)&t;
}
static __device__ __forceinline__ float tanh_fast(float x) {
    float e = __expf(2.0f * x);
    return 1.0f - __fdividef(2.0f, e + 1.0f);
}

// ---------------------------------------------------------------------------
// prepass: enc fp32 -> hi/lo bf16
// ---------------------------------------------------------------------------
__global__ void convert_enc_kernel(const float* __restrict__ enc) {
    size_t i = ((size_t)blockIdx.x * 256 + threadIdx.x) * 8;
    float4 v0 = *(const float4*)(enc + i);
    float4 v1 = *(const float4*)(enc + i + 4);
    uint4 hi, lo;
    hi.x = pack2(v0.x, v0.y); hi.y = pack2(v0.z, v0.w);
    hi.z = pack2(v1.x, v1.y); hi.w = pack2(v1.z, v1.w);
    __nv_bfloat162 h;
    *(uint32_t*)&h = hi.x;
    lo.x = pack2(v0.x - __bfloat162float(h.x), v0.y - __bfloat162float(h.y));
    *(uint32_t*)&h = hi.y;
    lo.y = pack2(v0.z - __bfloat162float(h.x), v0.w - __bfloat162float(h.y));
    *(uint32_t*)&h = hi.z;
    lo.z = pack2(v1.x - __bfloat162float(h.x), v1.y - __bfloat162float(h.y));
    *(uint32_t*)&h = hi.w;
    lo.w = pack2(v1.z - __bfloat162float(h.x), v1.w - __bfloat162float(h.y));
    *(uint4*)(g_enc_hi + i) = hi;
    *(uint4*)(g_enc_lo + i) = lo;
}

__global__ void convert_w1_kernel(const float* __restrict__ W1) {
    int i = blockIdx.x * blockDim.x + threadIdx.x;   // u*ND + d
    int u = i >> 9, d = i & 511;
    float x = W1[d * NU + u];
    __nv_bfloat16 h = __float2bfloat16(x);
    g_w1t_hi[i] = h;
    g_w1t_lo[i] = __float2bfloat16(x - __bfloat162float(h));
}

// decp: grid (NB, 4) x 128 threads; block handles 128 u's of one batch.
__global__ void decp_kernel(const float* __restrict__ dec, const float* __restrict__ W2,
                            const float* __restrict__ b1, const float* __restrict__ b2) {
    const int b = blockIdx.x;
    const int u = blockIdx.y * 128 + threadIdx.x;
    __shared__ float ds[ND];
    for (int i = threadIdx.x; i < ND; i += 128) ds[i] = dec[b * ND + i];
    __syncthreads();
    float a0 = 0.f, a1 = 0.f, a2 = 0.f, a3 = 0.f;
#pragma unroll 4
    for (int d = 0; d < ND; d += 4) {
        a0 += ds[d + 0] * W2[(d + 0) * NU + u];
        a1 += ds[d + 1] * W2[(d + 1) * NU + u];
        a2 += ds[d + 2] * W2[(d + 2) * NU + u];
        a3 += ds[d + 3] * W2[(d + 3) * NU + u];
    }
    g_decp[b * NU + u] = (a0 + a1) + (a2 + a3) + b1[u] + b2[u];
}

// ---------------------------------------------------------------------------
// GEMM: mma.sync bf16 3-term split, cp.async 2-stage pipeline, k-chunk 32.
// grid (4 coltiles [fast], 1024 rowtiles) -> wave shares A panels via L2.
// ---------------------------------------------------------------------------
#define STAGE_BYTES 32768
#define SMEM_BYTES  (2 * STAGE_BYTES)
#define NCHUNK      16

__global__ __launch_bounds__(256, 2)
void score_gemm_mma(const float* __restrict__ V) {
    extern __shared__ char sm[];
    const uint32_t uBase = smem_u32(sm);

    const int tid = threadIdx.x;
    const int w = tid >> 5;
    const int lane = tid & 31;
    const int coltile = blockIdx.x;
    const int rowBase = blockIdx.y * 128;
    const int colBase = coltile * 128;
    const int b = rowBase / NS;

    const int wm = (w & 1) * 64;
    const int wn = (w >> 1) * 32;

    const int row0 = tid >> 2;
    const int g0 = tid & 3;
    const uint32_t so0 = sw64(row0 * 64 + g0 * 16);
    const uint32_t so1 = sw64((row0 + 64) * 64 + g0 * 16);
    const size_t aoff0 = (size_t)(rowBase + row0) * ND + g0 * 8;
    const size_t aoff1 = aoff0 + (size_t)64 * ND;
    const size_t boff0 = (size_t)(colBase + row0) * ND + g0 * 8;
    const size_t boff1 = boff0 + (size_t)64 * ND;

    const int aKH = (lane >> 4) * 16;
    const int bKH = ((lane >> 3) & 1) * 16;
    int pA[4], xA[4];
#pragma unroll
    for (int mt = 0; mt < 4; mt++) {
        int r = wm + mt * 16 + (lane & 15);
        pA[mt] = r * 64;
        xA[mt] = ((r >> 1) & 3) << 4;
    }
    int pB[2], xB[2];
#pragma unroll
    for (int nt2 = 0; nt2 < 2; nt2++) {
        int r = wn + nt2 * 16 + (lane & 7) + ((lane >> 4) << 3);
        pB[nt2] = r * 64;
        xB[nt2] = ((r >> 1) & 3) << 4;
    }

    float c[4][4][4];
#pragma unroll
    for (int i = 0; i < 4; i++)
#pragma unroll
        for (int j = 0; j < 4; j++)
#pragma unroll
            for (int k = 0; k < 4; k++) c[i][j][k] = 0.f;

    {
        const uint32_t sb = uBase;
        cp16(sb + so0, g_enc_hi + aoff0);
        cp16(sb + so1, g_enc_hi + aoff1);
        cp16(sb + 8192 + so0, g_enc_lo + aoff0);
        cp16(sb + 8192 + so1, g_enc_lo + aoff1);
        cp16(sb + 16384 + so0, g_w1t_hi + boff0);
        cp16(sb + 16384 + so1, g_w1t_hi + boff1);
        cp16(sb + 24576 + so0, g_w1t_lo + boff0);
        cp16(sb + 24576 + so1, g_w1t_lo + boff1);
        CP_COMMIT();
    }

    for (int cc = 0; cc < NCHUNK; cc++) {
        if (cc + 1 < NCHUNK) {
            const int k1 = (cc + 1) * 32;
            const uint32_t sb = uBase + ((cc + 1) & 1) * STAGE_BYTES;
            cp16(sb + so0, g_enc_hi + aoff0 + k1);
            cp16(sb + so1, g_enc_hi + aoff1 + k1);
            cp16(sb + 8192 + so0, g_enc_lo + aoff0 + k1);
            cp16(sb + 8192 + so1, g_enc_lo + aoff1 + k1);
            cp16(sb + 16384 + so0, g_w1t_hi + boff0 + k1);
            cp16(sb + 16384 + so1, g_w1t_hi + boff1 + k1);
            cp16(sb + 24576 + so0, g_w1t_lo + boff0 + k1);
            cp16(sb + 24576 + so1, g_w1t_lo + boff1 + k1);
            CP_COMMIT();
            CP_WAIT1();
        } else {
            CP_WAIT0();
        }
        __syncthreads();

        const uint32_t uAh = uBase + (cc & 1) * STAGE_BYTES;
        const uint32_t uAl = uAh + 8192;
        const uint32_t uBh = uAh + 16384;
        const uint32_t uBl = uAh + 24576;

#pragma unroll
        for (int s = 0; s < 2; s++) {
            const int kb = s * 32;
            uint32_t ah[4][4], al[4][4], bh[2][4], bl[2][4];
#pragma unroll
            for (int mt = 0; mt < 4; mt++)
                ldmx4(ah[mt], uAh + pA[mt] + ((kb + aKH) ^ xA[mt]));
#pragma unroll
            for (int nt2 = 0; nt2 < 2; nt2++)
                ldmx4(bh[nt2], uBh + pB[nt2] + ((kb + bKH) ^ xB[nt2]));
#pragma unroll
            for (int mt = 0; mt < 4; mt++)
#pragma unroll
                for (int nt = 0; nt < 4; nt++)
                    mma_bf16(c[mt][nt], ah[mt], &bh[nt >> 1][(nt & 1) * 2]);

#pragma unroll
            for (int nt2 = 0; nt2 < 2; nt2++)
                ldmx4(bl[nt2], uBl + pB[nt2] + ((kb + bKH) ^ xB[nt2]));
#pragma unroll
            for (int mt = 0; mt < 4; mt++)
#pragma unroll
                for (int nt = 0; nt < 4; nt++)
                    mma_bf16(c[mt][nt], ah[mt], &bl[nt >> 1][(nt & 1) * 2]);

#pragma unroll
            for (int mt = 0; mt < 4; mt++)
                ldmx4(al[mt], uAl + pA[mt] + ((kb + aKH) ^ xA[mt]));
#pragma unroll
            for (int mt = 0; mt < 4; mt++)
#pragma unroll
                for (int nt = 0; nt < 4; nt++)
                    mma_bf16(c[mt][nt], al[mt], &bh[nt >> 1][(nt & 1) * 2]);
        }
        __syncthreads();
    }

    // ---- epilogue: tanh + V-dot, lane reduce, plain store per coltile ----
    float dv[8], vv[8];
#pragma unroll
    for (int nt = 0; nt < 4; nt++) {
#pragma unroll
        for (int i = 0; i < 2; i++) {
            int col = colBase + wn + nt * 8 + (lane & 3) * 2 + i;
            dv[nt * 2 + i] = g_decp[b * NU + col];
            vv[nt * 2 + i] = V[col];
        }
    }
    float rowsum[4][2];
#pragma unroll
    for (int mt = 0; mt < 4; mt++) {
#pragma unroll
        for (int h = 0; h < 2; h++) {
            float s = 0.f;
#pragma unroll
            for (int nt = 0; nt < 4; nt++) {
#pragma unroll
                for (int i = 0; i < 2; i++) {
                    float x = c[mt][nt][h * 2 + i] + dv[nt * 2 + i];
                    s += tanh_fast(x) * vv[nt * 2 + i];
                }
            }
            rowsum[mt][h] = s;
        }
    }
#pragma unroll
    for (int mt = 0; mt < 4; mt++) {
#pragma unroll
        for (int h = 0; h < 2; h++) {
            float s = rowsum[mt][h];
            s += __shfl_xor_sync(0xffffffffu, s, 1);
            s += __shfl_xor_sync(0xffffffffu, s, 2);
            rowsum[mt][h] = s;
        }
    }
    // 4 warps cover the 128 cols of this coltile for the same 64 rows;
    // reduce across them via smem, then one plain store per row.
    __shared__ float sred[2][128];
    if (tid < 128) { sred[0][tid] = 0.f; }
    if (tid >= 128) { sred[1][tid - 128] = 0.f; }
    __syncthreads();
    if ((lane & 3) == 0) {
#pragma unroll
        for (int mt = 0; mt < 4; mt++)
#pragma unroll
            for (int h = 0; h < 2; h++) {
                int rloc = mt * 16 + (lane >> 2) + h * 8;   // 0..63
                atomicAdd(&sred[w & 1][rloc], rowsum[mt][h]);
            }
    }
    __syncthreads();
    if (tid < 128) {
        float s = sred[tid >> 6][tid & 63];
        g_score_part[coltile][rowBase + (tid >> 6) * 64 + (tid & 63)] = s;
    }
}

// ---------------------------------------------------------------------------
// softmax: score = bv + sum of 4 coltile partials
// ---------------------------------------------------------------------------
__global__ void softmax_kernel(float* __restrict__ out, const float* __restrict__ bv) {
    const int b = blockIdx.x;
    const int t = threadIdx.x;
    __shared__ float redbuf[32];
    __shared__ float s_max, s_sum;
    const float bvv = bv[0];

    float v[4];
    float m = -3.4e38f;
#pragma unroll
    for (int i = 0; i < 4; i++) {
        int idx = b * NS + t + i * 1024;
        v[i] = bvv + g_score_part[0][idx] + g_score_part[1][idx] +
               g_score_part[2][idx] + g_score_part[3][idx];
        m = fmaxf(m, v[i]);
    }
#pragma unroll
    for (int o = 16; o > 0; o >>= 1) m = fmaxf(m, __shfl_xor_sync(0xffffffffu, m, o));
    if ((t & 31) == 0) redbuf[t >> 5] = m;
    __syncthreads();
    if (t < 32) {
        float x = redbuf[t];
#pragma unroll
        for (int o = 16; o > 0; o >>= 1) x = fmaxf(x, __shfl_xor_sync(0xffffffffu, x, o));
        if (t == 0) s_max = x;
    }
    __syncthreads();
    const float bm = s_max;
    float e[4], s = 0.f;
#pragma unroll
    for (int i = 0; i < 4; i++) { e[i] = __expf(v[i] - bm); s += e[i]; }
#pragma unroll
    for (int o = 16; o > 0; o >>= 1) s += __shfl_xor_sync(0xffffffffu, s, o);
    if ((t & 31) == 0) redbuf[t >> 5] = s;
    __syncthreads();
    if (t < 32) {
        float x = redbuf[t];
#pragma unroll
        for (int o = 16; o > 0; o >>= 1) x += __shfl_xor_sync(0xffffffffu, x, o);
        if (t == 0) s_sum = x;
    }
    __syncthreads();
    const float inv = 1.0f / s_sum;
#pragma unroll
    for (int i = 0; i < 4; i++) out[NB * ND + b * NS + t + i * 1024] = e[i] * inv;
}

__global__ void ctx_part_kernel(const float* __restrict__ enc, const float* __restrict__ out) {
    const int b = blockIdx.x >> 5;
    const int chunk = blockIdx.x & 31;
    const int d = threadIdx.x;
    __shared__ float ws[128];
    const float* w = out + NB * ND + b * NS + chunk * 128;
    if (d < 128) ws[d] = w[d];
    __syncthreads();
    const float* ep = enc + ((size_t)(b * NS + chunk * 128)) * ND + d;
    float acc = 0.f;
#pragma unroll 8
    for (int s = 0; s < 128; s++) acc += ws[s] * ep[(size_t)s * ND];
    g_ctx_part[((size_t)chunk * NB + b) * ND + d] = acc;
}

__global__ void ctx_reduce_kernel(float* __restrict__ out) {
    const int b = blockIdx.x;
    const int d = threadIdx.x;
    float acc = 0.f;
#pragma unroll
    for (int c = 0; c < 32; c++) acc += g_ctx_part[((size_t)c * NB + b) * ND + d];
    out[b * ND + d] = acc;
}

// ---------------------------------------------------------------------------
extern "C" void kernel_launch(void* const* d_in, const int* in_sizes, int n_in,
                              void* d_out, int out_size) {
    const float* enc = (const float*)d_in[0];
    const float* dec = (const float*)d_in[1];
    const float* W1  = (const float*)d_in[2];
    const float* b1  = (const float*)d_in[3];
    const float* W2  = (const float*)d_in[4];
    const float* b2  = (const float*)d_in[5];
    const float* V   = (const float*)d_in[6];
    const float* bv  = (const float*)d_in[7];
    float* out = (float*)d_out;

    cudaFuncSetAttribute(score_gemm_mma, cudaFuncAttributeMaxDynamicSharedMemorySize,
                         SMEM_BYTES);

    convert_enc_kernel<<<(size_t)NM * ND / (256 * 8), 256>>>(enc);
    convert_w1_kernel<<<NU * ND / 256, 256>>>(W1);
    decp_kernel<<<dim3(NB, 4), 128>>>(dec, W2, b1, b2);
    score_gemm_mma<<<dim3(NU / 128, NM / 128), 256, SMEM_BYTES>>>(V);
    softmax_kernel<<<NB, 1024>>>(out, bv);
    ctx_part_kernel<<<NB * 32, ND>>>(enc, out);
    ctx_reduce_kernel<<<NB, ND>>>(out);
}

// round 8
// speedup vs baseline: 1.0130x; 1.0130x over previous
#include <cuda_runtime.h>
#include <cuda_bf16.h>
#include <cstdint>

#define NB 32
#define NS 4096
#define ND 512
#define NU 512
#define NM (NB * NS)

// ---------------- device scratch ----------------
__device__ float g_score_part[4][NB * NS];   // per-coltile score partials
__device__ float g_decp[NB * NU];
__device__ float g_ctx_part[32 * NB * ND];
__device__ __nv_bfloat16 g_enc_hi[(size_t)NM * ND];
__device__ __nv_bfloat16 g_enc_lo[(size_t)NM * ND];
__device__ __nv_bfloat16 g_w1t_hi[NU * ND];
__device__ __nv_bfloat16 g_w1t_lo[NU * ND];

// ---------------- helpers ----------------
static __device__ __forceinline__ uint32_t smem_u32(const void* p) {
    uint32_t a;
    asm("{ .reg .u64 t; cvta.to.shared.u64 t, %1; cvt.u32.u64 %0, t; }" : "=r"(a) : "l"(p));
    return a;
}
static __device__ __forceinline__ void ldmx4(uint32_t* r, uint32_t addr) {
    asm volatile("ldmatrix.sync.aligned.m8n8.x4.shared.b16 {%0,%1,%2,%3}, [%4];"
                 : "=r"(r[0]), "=r"(r[1]), "=r"(r[2]), "=r"(r[3]) : "r"(addr));
}
static __device__ __forceinline__ void mma_bf16(float* c, const uint32_t* a, const uint32_t* b) {
    asm volatile(
        "mma.sync.aligned.m16n8k16.row.col.f32.bf16.bf16.f32 "
        "{%0,%1,%2,%3}, {%4,%5,%6,%7}, {%8,%9}, {%0,%1,%2,%3};"
        : "+f"(c[0]), "+f"(c[1]), "+f"(c[2]), "+f"(c[3])
        : "r"(a[0]), "r"(a[1]), "r"(a[2]), "r"(a[3]), "r"(b[0]), "r"(b[1]));
}
static __device__ __forceinline__ void cp16(uint32_t s, const void* g) {
    asm volatile("cp.async.cg.shared.global [%0], [%1], 16;" :: "r"(s), "l"(g));
}
#define CP_COMMIT() asm volatile("cp.async.commit_group;" ::: "memory")
#define CP_WAIT1()  asm volatile("cp.async.wait_group 1;" ::: "memory")
#define CP_WAIT0()  asm volatile("cp.async.wait_group 0;" ::: "memory")

static __device__ __forceinline__ uint32_t sw64(uint32_t o) { return o ^ ((o >> 3) & 0x30); }
static __device__ __forceinline__ uint32_t pack2(float x, float y) {
    __nv_bfloat162 t = __floats2bfloat162_rn(x, y);
    return *(uint32_t*)&t;
}
static __device__ __forceinline__ float tanh_fast(float x) {
    float e = __expf(2.0f * x);
    return 1.0f - __fdividef(2.0f, e + 1.0f);
}

// ---------------------------------------------------------------------------
// prepass: enc fp32 -> hi/lo bf16 (pure stream: bypass-cache hints)
// ---------------------------------------------------------------------------
__global__ void convert_enc_kernel(const float* __restrict__ enc) {
    size_t i = ((size_t)blockIdx.x * 256 + threadIdx.x) * 8;
    float4 v0 = __ldcs((const float4*)(enc + i));
    float4 v1 = __ldcs((const float4*)(enc + i + 4));
    uint4 hi, lo;
    hi.x = pack2(v0.x, v0.y); hi.y = pack2(v0.z, v0.w);
    hi.z = pack2(v1.x, v1.y); hi.w = pack2(v1.z, v1.w);
    __nv_bfloat162 h;
    *(uint32_t*)&h = hi.x;
    lo.x = pack2(v0.x - __bfloat162float(h.x), v0.y - __bfloat162float(h.y));
    *(uint32_t*)&h = hi.y;
    lo.y = pack2(v0.z - __bfloat162float(h.x), v0.w - __bfloat162float(h.y));
    *(uint32_t*)&h = hi.z;
    lo.z = pack2(v1.x - __bfloat162float(h.x), v1.y - __bfloat162float(h.y));
    *(uint32_t*)&h = hi.w;
    lo.w = pack2(v1.z - __bfloat162float(h.x), v1.w - __bfloat162float(h.y));
    __stcs((uint4*)(g_enc_hi + i), hi);
    __stcs((uint4*)(g_enc_lo + i), lo);
}

__global__ void convert_w1_kernel(const float* __restrict__ W1) {
    int i = blockIdx.x * blockDim.x + threadIdx.x;   // u*ND + d
    int u = i >> 9, d = i & 511;
    float x = W1[d * NU + u];
    __nv_bfloat16 h = __float2bfloat16(x);
    g_w1t_hi[i] = h;
    g_w1t_lo[i] = __float2bfloat16(x - __bfloat162float(h));
}

// decp: grid (NB, 4) x 128 threads; block handles 128 u's of one batch.
__global__ void decp_kernel(const float* __restrict__ dec, const float* __restrict__ W2,
                            const float* __restrict__ b1, const float* __restrict__ b2) {
    const int b = blockIdx.x;
    const int u = blockIdx.y * 128 + threadIdx.x;
    __shared__ float ds[ND];
    for (int i = threadIdx.x; i < ND; i += 128) ds[i] = dec[b * ND + i];
    __syncthreads();
    float a0 = 0.f, a1 = 0.f, a2 = 0.f, a3 = 0.f;
#pragma unroll 4
    for (int d = 0; d < ND; d += 4) {
        a0 += ds[d + 0] * W2[(d + 0) * NU + u];
        a1 += ds[d + 1] * W2[(d + 1) * NU + u];
        a2 += ds[d + 2] * W2[(d + 2) * NU + u];
        a3 += ds[d + 3] * W2[(d + 3) * NU + u];
    }
    g_decp[b * NU + u] = (a0 + a1) + (a2 + a3) + b1[u] + b2[u];
}

// ---------------------------------------------------------------------------
// GEMM: mma.sync bf16 3-term split, cp.async 3-stage pipeline, k-chunk 32.
// grid (4 coltiles [fast], 1024 rowtiles); one __syncthreads per chunk.
// ---------------------------------------------------------------------------
#define STAGE_BYTES 32768
#define NSTAGE      3
#define SMEM_BYTES  (NSTAGE * STAGE_BYTES)
#define NCHUNK      16

__global__ __launch_bounds__(256, 2)
void score_gemm_mma(const float* __restrict__ V) {
    extern __shared__ char sm[];
    const uint32_t uBase = smem_u32(sm);

    const int tid = threadIdx.x;
    const int w = tid >> 5;
    const int lane = tid & 31;
    const int coltile = blockIdx.x;
    const int rowBase = blockIdx.y * 128;
    const int colBase = coltile * 128;
    const int b = rowBase / NS;

    const int wm = (w & 1) * 64;
    const int wn = (w >> 1) * 32;

    const int row0 = tid >> 2;
    const int g0 = tid & 3;
    const uint32_t so0 = sw64(row0 * 64 + g0 * 16);
    const uint32_t so1 = sw64((row0 + 64) * 64 + g0 * 16);
    const size_t aoff0 = (size_t)(rowBase + row0) * ND + g0 * 8;
    const size_t aoff1 = aoff0 + (size_t)64 * ND;
    const size_t boff0 = (size_t)(colBase + row0) * ND + g0 * 8;
    const size_t boff1 = boff0 + (size_t)64 * ND;

    const int aKH = (lane >> 4) * 16;
    const int bKH = ((lane >> 3) & 1) * 16;
    int pA[4], xA[4];
#pragma unroll
    for (int mt = 0; mt < 4; mt++) {
        int r = wm + mt * 16 + (lane & 15);
        pA[mt] = r * 64;
        xA[mt] = ((r >> 1) & 3) << 4;
    }
    int pB[2], xB[2];
#pragma unroll
    for (int nt2 = 0; nt2 < 2; nt2++) {
        int r = wn + nt2 * 16 + (lane & 7) + ((lane >> 4) << 3);
        pB[nt2] = r * 64;
        xB[nt2] = ((r >> 1) & 3) << 4;
    }

    float c[4][4][4];
#pragma unroll
    for (int i = 0; i < 4; i++)
#pragma unroll
        for (int j = 0; j < 4; j++)
#pragma unroll
            for (int k = 0; k < 4; k++) c[i][j][k] = 0.f;

    // prologue: issue chunks 0 and 1
#pragma unroll
    for (int p = 0; p < 2; p++) {
        const int k1 = p * 32;
        const uint32_t sb = uBase + p * STAGE_BYTES;
        cp16(sb + so0, g_enc_hi + aoff0 + k1);
        cp16(sb + so1, g_enc_hi + aoff1 + k1);
        cp16(sb + 8192 + so0, g_enc_lo + aoff0 + k1);
        cp16(sb + 8192 + so1, g_enc_lo + aoff1 + k1);
        cp16(sb + 16384 + so0, g_w1t_hi + boff0 + k1);
        cp16(sb + 16384 + so1, g_w1t_hi + boff1 + k1);
        cp16(sb + 24576 + so0, g_w1t_lo + boff0 + k1);
        cp16(sb + 24576 + so1, g_w1t_lo + boff1 + k1);
        CP_COMMIT();
    }

    for (int cc = 0; cc < NCHUNK; cc++) {
        // stage cc must be complete: outstanding groups <= (last_issued - cc)
        if (cc + 1 < NCHUNK) { CP_WAIT1(); } else { CP_WAIT0(); }
        __syncthreads();   // single barrier per chunk: also protects buffer (cc-1)%3

        const uint32_t uAh = uBase + (cc % NSTAGE) * STAGE_BYTES;
        const uint32_t uAl = uAh + 8192;
        const uint32_t uBh = uAh + 16384;
        const uint32_t uBl = uAh + 24576;

#pragma unroll
        for (int s = 0; s < 2; s++) {
            const int kb = s * 32;
            uint32_t ah[4][4], al[4][4], bh[2][4], bl[2][4];
#pragma unroll
            for (int mt = 0; mt < 4; mt++)
                ldmx4(ah[mt], uAh + pA[mt] + ((kb + aKH) ^ xA[mt]));
#pragma unroll
            for (int nt2 = 0; nt2 < 2; nt2++)
                ldmx4(bh[nt2], uBh + pB[nt2] + ((kb + bKH) ^ xB[nt2]));
#pragma unroll
            for (int mt = 0; mt < 4; mt++)
#pragma unroll
                for (int nt = 0; nt < 4; nt++)
                    mma_bf16(c[mt][nt], ah[mt], &bh[nt >> 1][(nt & 1) * 2]);

#pragma unroll
            for (int nt2 = 0; nt2 < 2; nt2++)
                ldmx4(bl[nt2], uBl + pB[nt2] + ((kb + bKH) ^ xB[nt2]));
#pragma unroll
            for (int mt = 0; mt < 4; mt++)
#pragma unroll
                for (int nt = 0; nt < 4; nt++)
                    mma_bf16(c[mt][nt], ah[mt], &bl[nt >> 1][(nt & 1) * 2]);

#pragma unroll
            for (int mt = 0; mt < 4; mt++)
                ldmx4(al[mt], uAl + pA[mt] + ((kb + aKH) ^ xA[mt]));
#pragma unroll
            for (int mt = 0; mt < 4; mt++)
#pragma unroll
                for (int nt = 0; nt < 4; nt++)
                    mma_bf16(c[mt][nt], al[mt], &bh[nt >> 1][(nt & 1) * 2]);
        }

        // issue chunk cc+2 into buffer (cc+2)%3 == (cc-1)%3 (compute done, barrier-proven)
        if (cc + 2 < NCHUNK) {
            const int k1 = (cc + 2) * 32;
            const uint32_t sb = uBase + ((cc + 2) % NSTAGE) * STAGE_BYTES;
            cp16(sb + so0, g_enc_hi + aoff0 + k1);
            cp16(sb + so1, g_enc_hi + aoff1 + k1);
            cp16(sb + 8192 + so0, g_enc_lo + aoff0 + k1);
            cp16(sb + 8192 + so1, g_enc_lo + aoff1 + k1);
            cp16(sb + 16384 + so0, g_w1t_hi + boff0 + k1);
            cp16(sb + 16384 + so1, g_w1t_hi + boff1 + k1);
            cp16(sb + 24576 + so0, g_w1t_lo + boff0 + k1);
            cp16(sb + 24576 + so1, g_w1t_lo + boff1 + k1);
            CP_COMMIT();
        }
    }

    // ---- epilogue: tanh + V-dot, lane reduce, plain store per coltile ----
    float dv[8], vv[8];
#pragma unroll
    for (int nt = 0; nt < 4; nt++) {
#pragma unroll
        for (int i = 0; i < 2; i++) {
            int col = colBase + wn + nt * 8 + (lane & 3) * 2 + i;
            dv[nt * 2 + i] = g_decp[b * NU + col];
            vv[nt * 2 + i] = V[col];
        }
    }
    float rowsum[4][2];
#pragma unroll
    for (int mt = 0; mt < 4; mt++) {
#pragma unroll
        for (int h = 0; h < 2; h++) {
            float s = 0.f;
#pragma unroll
            for (int nt = 0; nt < 4; nt++) {
#pragma unroll
                for (int i = 0; i < 2; i++) {
                    float x = c[mt][nt][h * 2 + i] + dv[nt * 2 + i];
                    s += tanh_fast(x) * vv[nt * 2 + i];
                }
            }
            rowsum[mt][h] = s;
        }
    }
#pragma unroll
    for (int mt = 0; mt < 4; mt++) {
#pragma unroll
        for (int h = 0; h < 2; h++) {
            float s = rowsum[mt][h];
            s += __shfl_xor_sync(0xffffffffu, s, 1);
            s += __shfl_xor_sync(0xffffffffu, s, 2);
            rowsum[mt][h] = s;
        }
    }
    // 4 warps cover the 128 cols of this coltile for the same 64 rows;
    // reduce across them via smem, then one plain store per row.
    __shared__ float sred[2][128];
    __syncthreads();
    if (tid < 128) { sred[0][tid] = 0.f; }
    if (tid >= 128) { sred[1][tid - 128] = 0.f; }
    __syncthreads();
    if ((lane & 3) == 0) {
#pragma unroll
        for (int mt = 0; mt < 4; mt++)
#pragma unroll
            for (int h = 0; h < 2; h++) {
                int rloc = mt * 16 + (lane >> 2) + h * 8;   // 0..63
                atomicAdd(&sred[w & 1][rloc], rowsum[mt][h]);
            }
    }
    __syncthreads();
    if (tid < 128) {
        float s = sred[tid >> 6][tid & 63];
        g_score_part[coltile][rowBase + (tid >> 6) * 64 + (tid & 63)] = s;
    }
}

// ---------------------------------------------------------------------------
// softmax: score = bv + sum of 4 coltile partials
// ---------------------------------------------------------------------------
__global__ void softmax_kernel(float* __restrict__ out, const float* __restrict__ bv) {
    const int b = blockIdx.x;
    const int t = threadIdx.x;
    __shared__ float redbuf[32];
    __shared__ float s_max, s_sum;
    const float bvv = bv[0];

    float v[4];
    float m = -3.4e38f;
#pragma unroll
    for (int i = 0; i < 4; i++) {
        int idx = b * NS + t + i * 1024;
        v[i] = bvv + g_score_part[0][idx] + g_score_part[1][idx] +
               g_score_part[2][idx] + g_score_part[3][idx];
        m = fmaxf(m, v[i]);
    }
#pragma unroll
    for (int o = 16; o > 0; o >>= 1) m = fmaxf(m, __shfl_xor_sync(0xffffffffu, m, o));
    if ((t & 31) == 0) redbuf[t >> 5] = m;
    __syncthreads();
    if (t < 32) {
        float x = redbuf[t];
#pragma unroll
        for (int o = 16; o > 0; o >>= 1) x = fmaxf(x, __shfl_xor_sync(0xffffffffu, x, o));
        if (t == 0) s_max = x;
    }
    __syncthreads();
    const float bm = s_max;
    float e[4], s = 0.f;
#pragma unroll
    for (int i = 0; i < 4; i++) { e[i] = __expf(v[i] - bm); s += e[i]; }
#pragma unroll
    for (int o = 16; o > 0; o >>= 1) s += __shfl_xor_sync(0xffffffffu, s, o);
    if ((t & 31) == 0) redbuf[t >> 5] = s;
    __syncthreads();
    if (t < 32) {
        float x = redbuf[t];
#pragma unroll
        for (int o = 16; o > 0; o >>= 1) x += __shfl_xor_sync(0xffffffffu, x, o);
        if (t == 0) s_sum = x;
    }
    __syncthreads();
    const float inv = 1.0f / s_sum;
#pragma unroll
    for (int i = 0; i < 4; i++) out[NB * ND + b * NS + t + i * 1024] = e[i] * inv;
}

__global__ void ctx_part_kernel(const float* __restrict__ enc, const float* __restrict__ out) {
    const int b = blockIdx.x >> 5;
    const int chunk = blockIdx.x & 31;
    const int d = threadIdx.x;
    __shared__ float ws[128];
    const float* w = out + NB * ND + b * NS + chunk * 128;
    if (d < 128) ws[d] = w[d];
    __syncthreads();
    const float* ep = enc + ((size_t)(b * NS + chunk * 128)) * ND + d;
    float acc = 0.f;
#pragma unroll 8
    for (int s = 0; s < 128; s++) acc += ws[s] * __ldcs(ep + (size_t)s * ND);
    g_ctx_part[((size_t)chunk * NB + b) * ND + d] = acc;
}

__global__ void ctx_reduce_kernel(float* __restrict__ out) {
    const int b = blockIdx.x;
    const int d = threadIdx.x;
    float acc = 0.f;
#pragma unroll
    for (int c = 0; c < 32; c++) acc += g_ctx_part[((size_t)c * NB + b) * ND + d];
    out[b * ND + d] = acc;
}

// ---------------------------------------------------------------------------
extern "C" void kernel_launch(void* const* d_in, const int* in_sizes, int n_in,
                              void* d_out, int out_size) {
    const float* enc = (const float*)d_in[0];
    const float* dec = (const float*)d_in[1];
    const float* W1  = (const float*)d_in[2];
    const float* b1  = (const float*)d_in[3];
    const float* W2  = (const float*)d_in[4];
    const float* b2  = (const float*)d_in[5];
    const float* V   = (const float*)d_in[6];
    const float* bv  = (const float*)d_in[7];
    float* out = (float*)d_out;

    cudaFuncSetAttribute(score_gemm_mma, cudaFuncAttributeMaxDynamicSharedMemorySize,
                         SMEM_BYTES);

    convert_enc_kernel<<<(size_t)NM * ND / (256 * 8), 256>>>(enc);
    convert_w1_kernel<<<NU * ND / 256, 256>>>(W1);
    decp_kernel<<<dim3(NB, 4), 128>>>(dec, W2, b1, b2);
    score_gemm_mma<<<dim3(NU / 128, NM / 128), 256, SMEM_BYTES>>>(V);
    softmax_kernel<<<NB, 1024>>>(out, bv);
    ctx_part_kernel<<<NB * 32, ND>>>(enc, out);
    ctx_reduce_kernel<<<NB, ND>>>(out);
}